// round 2
// baseline (speedup 1.0000x reference)
#include <cuda_runtime.h>
#include <cuda_fp16.h>
#include <cstdint>

#define DINL __device__ __forceinline__

namespace {
constexpr int KDIM = 4096;   // in_features
constexpr int NOUT = 4096;   // out_features
constexpr int MTOK = 1024;   // tokens

constexpr int BM = 128;      // CTA tile M
constexpr int BN = 256;      // CTA tile N
constexpr int BK = 32;       // K per stage
constexpr int NUM_K = KDIM / BK;   // 128
constexpr int STAGES = 4;
constexpr int THREADS = 256;

constexpr int A_ROW_B = 80;                 // 32 halves (64B) + 16B pad -> conflict-free ldmatrix
constexpr int B_ROW_B = 80;
constexpr int A_BYTES = BM * A_ROW_B;       // 10240
constexpr int B_BYTES = BN * B_ROW_B;       // 20480
constexpr int STAGE_BYTES = A_BYTES + B_BYTES;   // 30720
constexpr int SMEM_TOTAL = STAGES * STAGE_BYTES; // 122880
}  // namespace

// Scratch (static device globals: allowed; no runtime allocation).
__device__ __align__(16) __half   g_xh[(size_t)MTOK * KDIM];          // 8 MB fp16 x
__device__ __align__(16) unsigned g_wbits[(KDIM / 32) * NOUT];        // 2 MB packed binarized W, [kchunk][n]

DINL uint32_t smem_u32(const void* p) {
    uint32_t a;
    asm("{ .reg .u64 t; cvta.to.shared.u64 t, %1; cvt.u32.u64 %0, t; }" : "=r"(a) : "l"(p));
    return a;
}

// ---------------- prepass 1: x (f32) -> fp16 ----------------
__global__ void __launch_bounds__(256) conv_x_kernel(const float* __restrict__ x) {
    int i = blockIdx.x * blockDim.x + threadIdx.x;      // < MTOK*KDIM/4
    float4 v = ((const float4*)x)[i];
    __half2 h0 = __floats2half2_rn(v.x, v.y);
    __half2 h1 = __floats2half2_rn(v.z, v.w);
    uint2 u;
    u.x = *(const uint32_t*)&h0;
    u.y = *(const uint32_t*)&h1;
    *(uint2*)(&g_xh[(size_t)i * 4]) = u;
}

// ---------------- prepass 2: binarize + bit-pack W ----------------
// g_wbits[c * NOUT + n] bit j  =  (w[n][c*32 + j] > 0)
__global__ void __launch_bounds__(256) pack_w_kernel(const float* __restrict__ w) {
    int gtid = blockIdx.x * blockDim.x + threadIdx.x;
    int wgid = gtid >> 5;                  // global warp id, < (KDIM/32)*NOUT
    int lane = threadIdx.x & 31;
    int n = wgid & (NOUT - 1);
    int c = wgid >> 12;
    float v = w[(size_t)n * KDIM + c * 32 + lane];
    unsigned m = __ballot_sync(0xFFFFFFFFu, v > 0.0f);
    if (lane == 0) g_wbits[c * NOUT + n] = m;
}

// ---------------- main GEMM: out = (x_fp16 @ Wb^T) * round(max(s,1)) ----------------
__global__ void __launch_bounds__(THREADS, 1)
SBNLinear_39754217292616_kernel(const float* __restrict__ s, float* __restrict__ out) {
    extern __shared__ char smem[];
    const uint32_t sb = smem_u32(smem);
    const int tid = threadIdx.x;
    const int lane = tid & 31;
    const int wid = tid >> 5;
    const int m0 = blockIdx.x * BM;
    const int n0 = blockIdx.y * BN;
    const int m_off = (wid >> 2) * 64;     // 2 warps in M
    const int n_off = (wid & 3) * 64;      // 4 warps in N

    float acc[4][8][4];
    #pragma unroll
    for (int mi = 0; mi < 4; ++mi)
        #pragma unroll
        for (int nj = 0; nj < 8; ++nj)
            #pragma unroll
            for (int e = 0; e < 4; ++e) acc[mi][nj][e] = 0.0f;

    // issue A-tile cp.async for k-chunk c into buffer buf
    auto issueA = [&](int c, int buf) {
        #pragma unroll
        for (int i = 0; i < 2; ++i) {
            int q = tid + i * THREADS;          // 0..511
            int row = q >> 2;
            int ch = q & 3;
            uint32_t dst = sb + buf * STAGE_BYTES + row * A_ROW_B + ch * 16;
            const __half* src = &g_xh[(size_t)(m0 + row) * KDIM + c * BK + ch * 8];
            asm volatile("cp.async.cg.shared.global [%0], [%1], 16;\n" :: "r"(dst), "l"(src) : "memory");
        }
    };
    // expand 32 W-bits of row n=tid into fp16 {0,1} and store into buffer buf
    auto stsB = [&](unsigned bits, int buf) {
        uint32_t dst = sb + buf * STAGE_BYTES + A_BYTES + tid * B_ROW_B;
        #pragma unroll
        for (int j = 0; j < 4; ++j) {
            uint32_t u0, u1, u2, u3;
            int p = j * 8;
            u0 = ((bits >> (p + 0)) & 1 ? 0x3C00u : 0u) | ((bits >> (p + 1)) & 1 ? 0x3C000000u : 0u);
            u1 = ((bits >> (p + 2)) & 1 ? 0x3C00u : 0u) | ((bits >> (p + 3)) & 1 ? 0x3C000000u : 0u);
            u2 = ((bits >> (p + 4)) & 1 ? 0x3C00u : 0u) | ((bits >> (p + 5)) & 1 ? 0x3C000000u : 0u);
            u3 = ((bits >> (p + 6)) & 1 ? 0x3C00u : 0u) | ((bits >> (p + 7)) & 1 ? 0x3C000000u : 0u);
            asm volatile("st.shared.v4.b32 [%0], {%1,%2,%3,%4};\n"
                         :: "r"(dst + j * 16), "r"(u0), "r"(u1), "r"(u2), "r"(u3) : "memory");
        }
    };

    // prologue: stages 0..2
    #pragma unroll
    for (int c = 0; c < STAGES - 1; ++c) {
        issueA(c, c);
        asm volatile("cp.async.commit_group;\n" ::: "memory");
        unsigned bits = g_wbits[c * NOUT + n0 + tid];
        stsB(bits, c);
    }
    unsigned bits_next = g_wbits[3 * NOUT + n0 + tid];   // for stage 3

    for (int c = 0; c < NUM_K; ++c) {
        const int buf = c & 3;
        if (c < NUM_K - 2)       asm volatile("cp.async.wait_group 2;\n" ::: "memory");
        else if (c == NUM_K - 2) asm volatile("cp.async.wait_group 1;\n" ::: "memory");
        else                     asm volatile("cp.async.wait_group 0;\n" ::: "memory");
        __syncthreads();

        const int cn = c + 3;
        if (cn < NUM_K) {
            const int nbuf = cn & 3;
            stsB(bits_next, nbuf);            // bits were prefetched last iter
            issueA(cn, nbuf);
            asm volatile("cp.async.commit_group;\n" ::: "memory");
            if (cn + 1 < NUM_K)
                bits_next = g_wbits[(cn + 1) * NOUT + n0 + tid];   // latency hides under MMAs
        }

        const uint32_t ab = sb + buf * STAGE_BYTES;
        const uint32_t bb = ab + A_BYTES;
        #pragma unroll
        for (int h = 0; h < 2; ++h) {
            uint32_t a[4][4], b[8][2];
            #pragma unroll
            for (int mi = 0; mi < 4; ++mi) {
                uint32_t addr = ab + (uint32_t)(m_off + 16 * mi + (lane & 15)) * A_ROW_B
                                   + (uint32_t)(2 * h + (lane >> 4)) * 16;
                asm volatile("ldmatrix.sync.aligned.m8n8.x4.shared.b16 {%0,%1,%2,%3}, [%4];\n"
                             : "=r"(a[mi][0]), "=r"(a[mi][1]), "=r"(a[mi][2]), "=r"(a[mi][3])
                             : "r"(addr));
            }
            #pragma unroll
            for (int g = 0; g < 4; ++g) {
                int row = n_off + 16 * g + ((lane >> 4) << 3) + (lane & 7);
                uint32_t addr = bb + (uint32_t)row * B_ROW_B
                                   + (uint32_t)(2 * h + ((lane >> 3) & 1)) * 16;
                uint32_t r0, r1, r2, r3;
                asm volatile("ldmatrix.sync.aligned.m8n8.x4.shared.b16 {%0,%1,%2,%3}, [%4];\n"
                             : "=r"(r0), "=r"(r1), "=r"(r2), "=r"(r3) : "r"(addr));
                b[2 * g][0] = r0; b[2 * g][1] = r1;
                b[2 * g + 1][0] = r2; b[2 * g + 1][1] = r3;
            }
            #pragma unroll
            for (int mi = 0; mi < 4; ++mi)
                #pragma unroll
                for (int nj = 0; nj < 8; ++nj) {
                    asm volatile(
                        "mma.sync.aligned.m16n8k16.row.col.f32.f16.f16.f32 "
                        "{%0,%1,%2,%3}, {%4,%5,%6,%7}, {%8,%9}, {%0,%1,%2,%3};\n"
                        : "+f"(acc[mi][nj][0]), "+f"(acc[mi][nj][1]),
                          "+f"(acc[mi][nj][2]), "+f"(acc[mi][nj][3])
                        : "r"(a[mi][0]), "r"(a[mi][1]), "r"(a[mi][2]), "r"(a[mi][3]),
                          "r"(b[nj][0]), "r"(b[nj][1]));
                }
        }
    }

    // epilogue: fuse s_eff = rint(max(s,1)) and store (full 32B sectors per mma row)
    float sc[8][2];
    #pragma unroll
    for (int nj = 0; nj < 8; ++nj) {
        int col = n0 + n_off + 8 * nj + 2 * (lane & 3);
        sc[nj][0] = rintf(fmaxf(s[col], 1.0f));
        sc[nj][1] = rintf(fmaxf(s[col + 1], 1.0f));
    }
    #pragma unroll
    for (int mi = 0; mi < 4; ++mi) {
        int r0 = m0 + m_off + 16 * mi + (lane >> 2);
        #pragma unroll
        for (int nj = 0; nj < 8; ++nj) {
            int col = n0 + n_off + 8 * nj + 2 * (lane & 3);
            float2 v0 = make_float2(acc[mi][nj][0] * sc[nj][0], acc[mi][nj][1] * sc[nj][1]);
            float2 v1 = make_float2(acc[mi][nj][2] * sc[nj][0], acc[mi][nj][3] * sc[nj][1]);
            *(float2*)(out + (size_t)r0 * NOUT + col) = v0;
            *(float2*)(out + (size_t)(r0 + 8) * NOUT + col) = v1;
        }
    }
}

extern "C" void kernel_launch(void* const* d_in, const int* in_sizes, int n_in,
                              void* d_out, int out_size) {
    (void)in_sizes; (void)n_in; (void)out_size;
    const float* x = (const float*)d_in[0];
    const float* w = (const float*)d_in[1];
    const float* s = (const float*)d_in[2];
    float* out = (float*)d_out;

    conv_x_kernel<<<(MTOK * KDIM / 4) / 256, 256>>>(x);
    pack_w_kernel<<<((KDIM / 32) * NOUT * 32) / 256, 256>>>(w);

    cudaFuncSetAttribute(SBNLinear_39754217292616_kernel,
                         cudaFuncAttributeMaxDynamicSharedMemorySize, SMEM_TOTAL);
    dim3 grid(MTOK / BM, NOUT / BN);   // 8 x 16 = 128 CTAs
    SBNLinear_39754217292616_kernel<<<grid, THREADS, SMEM_TOTAL>>>(s, out);
}

// round 3
// speedup vs baseline: 1.0644x; 1.0644x over previous
#include <cuda_runtime.h>
#include <cuda_fp16.h>
#include <cstdint>

#define DINL __device__ __forceinline__

namespace {
constexpr int KDIM = 4096;   // in_features
constexpr int NOUT = 4096;   // out_features
constexpr int MTOK = 1024;   // tokens

constexpr int BM = 128;      // CTA tile M
constexpr int BN = 256;      // CTA tile N
constexpr int BK = 32;       // K per stage
constexpr int NUM_K = KDIM / BK;   // 128
constexpr int STAGES = 4;
constexpr int THREADS = 256;

constexpr int A_ROW_B = 80;                 // 32 halves (64B) + 16B pad -> conflict-free ldmatrix
constexpr int B_ROW_B = 80;
constexpr int A_BYTES = BM * A_ROW_B;       // 10240
constexpr int B_BYTES = BN * B_ROW_B;       // 20480
constexpr int STAGE_BYTES = A_BYTES + B_BYTES;   // 30720
constexpr int SMEM_TOTAL = STAGES * STAGE_BYTES; // 122880

constexpr int CONV_BLOCKS = (MTOK * KDIM / 4) / 256;            // 4096
constexpr int PACK_BLOCKS = (NOUT * (KDIM / 128) * 32) / 256;   // 16384
}  // namespace

// Scratch (static device globals: allowed; no runtime allocation).
__device__ __align__(16) __half   g_xh[(size_t)MTOK * KDIM];          // 8 MB fp16 x
__device__ __align__(16) unsigned g_wbits[(KDIM / 32) * NOUT];        // 2 MB packed binarized W, [kchunk][n]

DINL uint32_t smem_u32(const void* p) {
    uint32_t a;
    asm("{ .reg .u64 t; cvta.to.shared.u64 t, %1; cvt.u32.u64 %0, t; }" : "=r"(a) : "l"(p));
    return a;
}

// ---------------- fused prepass: x->fp16  +  binarize/bit-pack W ----------------
__global__ void __launch_bounds__(256) prepass_kernel(const float* __restrict__ x,
                                                      const float* __restrict__ w) {
    if (blockIdx.x < CONV_BLOCKS) {
        int i = blockIdx.x * blockDim.x + threadIdx.x;
        float4 v = ((const float4*)x)[i];
        __half2 h0 = __floats2half2_rn(v.x, v.y);
        __half2 h1 = __floats2half2_rn(v.z, v.w);
        uint2 u;
        u.x = *(const uint32_t*)&h0;
        u.y = *(const uint32_t*)&h1;
        *(uint2*)(&g_xh[(size_t)i * 4]) = u;
    } else {
        // one warp packs 128 K-values (float4/lane) of one W row into 4 bit-words
        int pb = blockIdx.x - CONV_BLOCKS;
        int lane = threadIdx.x & 31;
        int wg = pb * 8 + (threadIdx.x >> 5);   // global warp id
        int n = wg & (NOUT - 1);
        int kb = wg >> 12;                      // 128-wide K block, 0..31
        const float4 v = *(const float4*)(w + (size_t)n * KDIM + kb * 128 + lane * 4);
        unsigned nib = (v.x > 0.f ? 1u : 0u) | (v.y > 0.f ? 2u : 0u)
                     | (v.z > 0.f ? 4u : 0u) | (v.w > 0.f ? 8u : 0u);
        unsigned a = nib | (__shfl_down_sync(0xFFFFFFFFu, nib, 1) << 4);
        unsigned b = a   | (__shfl_down_sync(0xFFFFFFFFu, a, 2)   << 8);
        unsigned m = b   | (__shfl_down_sync(0xFFFFFFFFu, b, 4)   << 16);
        if ((lane & 7) == 0) {
            int c = kb * 4 + (lane >> 3);
            g_wbits[c * NOUT + n] = m;
        }
    }
}

// ---------------- main GEMM: out = (x_fp16 @ Wb^T) * round(max(s,1)) ----------------
// f16-accumulate HMMA (2x rate) with fp32 promotion every 2 K-chunks.
__global__ void __launch_bounds__(THREADS, 1)
SBNLinear_39754217292616_kernel(const float* __restrict__ s, float* __restrict__ out) {
    extern __shared__ char smem[];
    const uint32_t sb = smem_u32(smem);
    const int tid = threadIdx.x;
    const int lane = tid & 31;
    const int wid = tid >> 5;
    const int m0 = blockIdx.x * BM;
    const int n0 = blockIdx.y * BN;
    const int m_off = (wid >> 2) * 64;     // 2 warps in M
    const int n_off = (wid & 3) * 64;      // 4 warps in N

    float acc32[4][8][4];
    uint32_t acc16[4][8][2];
    #pragma unroll
    for (int mi = 0; mi < 4; ++mi)
        #pragma unroll
        for (int nj = 0; nj < 8; ++nj) {
            acc16[mi][nj][0] = 0u; acc16[mi][nj][1] = 0u;
            #pragma unroll
            for (int e = 0; e < 4; ++e) acc32[mi][nj][e] = 0.0f;
        }

    auto issueA = [&](int c, int buf) {
        #pragma unroll
        for (int i = 0; i < 2; ++i) {
            int q = tid + i * THREADS;          // 0..511
            int row = q >> 2;
            int ch = q & 3;
            uint32_t dst = sb + buf * STAGE_BYTES + row * A_ROW_B + ch * 16;
            const __half* src = &g_xh[(size_t)(m0 + row) * KDIM + c * BK + ch * 8];
            asm volatile("cp.async.cg.shared.global [%0], [%1], 16;\n" :: "r"(dst), "l"(src) : "memory");
        }
    };
    auto stsB = [&](unsigned bits, int buf) {
        uint32_t dst = sb + buf * STAGE_BYTES + A_BYTES + tid * B_ROW_B;
        #pragma unroll
        for (int j = 0; j < 4; ++j) {
            uint32_t u0, u1, u2, u3;
            int p = j * 8;
            u0 = ((bits >> (p + 0)) & 1 ? 0x3C00u : 0u) | ((bits >> (p + 1)) & 1 ? 0x3C000000u : 0u);
            u1 = ((bits >> (p + 2)) & 1 ? 0x3C00u : 0u) | ((bits >> (p + 3)) & 1 ? 0x3C000000u : 0u);
            u2 = ((bits >> (p + 4)) & 1 ? 0x3C00u : 0u) | ((bits >> (p + 5)) & 1 ? 0x3C000000u : 0u);
            u3 = ((bits >> (p + 6)) & 1 ? 0x3C00u : 0u) | ((bits >> (p + 7)) & 1 ? 0x3C000000u : 0u);
            asm volatile("st.shared.v4.b32 [%0], {%1,%2,%3,%4};\n"
                         :: "r"(dst + j * 16), "r"(u0), "r"(u1), "r"(u2), "r"(u3) : "memory");
        }
    };

    // prologue: stages 0..2
    #pragma unroll
    for (int c = 0; c < STAGES - 1; ++c) {
        issueA(c, c);
        asm volatile("cp.async.commit_group;\n" ::: "memory");
        unsigned bits = g_wbits[c * NOUT + n0 + tid];
        stsB(bits, c);
    }
    unsigned bits_next = g_wbits[3 * NOUT + n0 + tid];

    for (int c = 0; c < NUM_K; ++c) {
        const int buf = c & 3;
        if (c < NUM_K - 2)       asm volatile("cp.async.wait_group 2;\n" ::: "memory");
        else if (c == NUM_K - 2) asm volatile("cp.async.wait_group 1;\n" ::: "memory");
        else                     asm volatile("cp.async.wait_group 0;\n" ::: "memory");
        __syncthreads();

        const int cn = c + 3;
        if (cn < NUM_K) {
            const int nbuf = cn & 3;
            stsB(bits_next, nbuf);
            issueA(cn, nbuf);
            asm volatile("cp.async.commit_group;\n" ::: "memory");
            if (cn + 1 < NUM_K)
                bits_next = g_wbits[(cn + 1) * NOUT + n0 + tid];
        }

        const uint32_t ab = sb + buf * STAGE_BYTES;
        const uint32_t bb = ab + A_BYTES;
        #pragma unroll
        for (int h = 0; h < 2; ++h) {
            uint32_t a[4][4];
            #pragma unroll
            for (int mi = 0; mi < 4; ++mi) {
                uint32_t addr = ab + (uint32_t)(m_off + 16 * mi + (lane & 15)) * A_ROW_B
                                   + (uint32_t)(2 * h + (lane >> 4)) * 16;
                asm volatile("ldmatrix.sync.aligned.m8n8.x4.shared.b16 {%0,%1,%2,%3}, [%4];\n"
                             : "=r"(a[mi][0]), "=r"(a[mi][1]), "=r"(a[mi][2]), "=r"(a[mi][3])
                             : "r"(addr));
            }
            #pragma unroll
            for (int g = 0; g < 4; ++g) {
                int row = n_off + 16 * g + ((lane >> 4) << 3) + (lane & 7);
                uint32_t addr = bb + (uint32_t)row * B_ROW_B
                                   + (uint32_t)(2 * h + ((lane >> 3) & 1)) * 16;
                uint32_t r0, r1, r2, r3;
                asm volatile("ldmatrix.sync.aligned.m8n8.x4.shared.b16 {%0,%1,%2,%3}, [%4];\n"
                             : "=r"(r0), "=r"(r1), "=r"(r2), "=r"(r3) : "r"(addr));
                #pragma unroll
                for (int mi = 0; mi < 4; ++mi) {
                    asm volatile(
                        "mma.sync.aligned.m16n8k16.row.col.f16.f16.f16.f16 "
                        "{%0,%1}, {%2,%3,%4,%5}, {%6,%7}, {%0,%1};\n"
                        : "+r"(acc16[mi][2 * g][0]), "+r"(acc16[mi][2 * g][1])
                        : "r"(a[mi][0]), "r"(a[mi][1]), "r"(a[mi][2]), "r"(a[mi][3]),
                          "r"(r0), "r"(r1));
                    asm volatile(
                        "mma.sync.aligned.m16n8k16.row.col.f16.f16.f16.f16 "
                        "{%0,%1}, {%2,%3,%4,%5}, {%6,%7}, {%0,%1};\n"
                        : "+r"(acc16[mi][2 * g + 1][0]), "+r"(acc16[mi][2 * g + 1][1])
                        : "r"(a[mi][0]), "r"(a[mi][1]), "r"(a[mi][2]), "r"(a[mi][3]),
                          "r"(r2), "r"(r3));
                }
            }
        }

        // promote f16 segment accumulators into fp32 every 2 chunks (64 K-steps)
        if (c & 1) {
            #pragma unroll
            for (int mi = 0; mi < 4; ++mi)
                #pragma unroll
                for (int nj = 0; nj < 8; ++nj) {
                    __half2 h0 = *(__half2*)&acc16[mi][nj][0];
                    __half2 h1 = *(__half2*)&acc16[mi][nj][1];
                    acc32[mi][nj][0] += __low2float(h0);
                    acc32[mi][nj][1] += __high2float(h0);
                    acc32[mi][nj][2] += __low2float(h1);
                    acc32[mi][nj][3] += __high2float(h1);
                    acc16[mi][nj][0] = 0u;
                    acc16[mi][nj][1] = 0u;
                }
        }
    }

    // epilogue: fuse s_eff = rint(max(s,1)) and store
    float sc[8][2];
    #pragma unroll
    for (int nj = 0; nj < 8; ++nj) {
        int col = n0 + n_off + 8 * nj + 2 * (lane & 3);
        sc[nj][0] = rintf(fmaxf(s[col], 1.0f));
        sc[nj][1] = rintf(fmaxf(s[col + 1], 1.0f));
    }
    #pragma unroll
    for (int mi = 0; mi < 4; ++mi) {
        int r0 = m0 + m_off + 16 * mi + (lane >> 2);
        #pragma unroll
        for (int nj = 0; nj < 8; ++nj) {
            int col = n0 + n_off + 8 * nj + 2 * (lane & 3);
            float2 v0 = make_float2(acc32[mi][nj][0] * sc[nj][0], acc32[mi][nj][1] * sc[nj][1]);
            float2 v1 = make_float2(acc32[mi][nj][2] * sc[nj][0], acc32[mi][nj][3] * sc[nj][1]);
            *(float2*)(out + (size_t)r0 * NOUT + col) = v0;
            *(float2*)(out + (size_t)(r0 + 8) * NOUT + col) = v1;
        }
    }
}

extern "C" void kernel_launch(void* const* d_in, const int* in_sizes, int n_in,
                              void* d_out, int out_size) {
    (void)in_sizes; (void)n_in; (void)out_size;
    const float* x = (const float*)d_in[0];
    const float* w = (const float*)d_in[1];
    const float* s = (const float*)d_in[2];
    float* out = (float*)d_out;

    prepass_kernel<<<CONV_BLOCKS + PACK_BLOCKS, 256>>>(x, w);

    cudaFuncSetAttribute(SBNLinear_39754217292616_kernel,
                         cudaFuncAttributeMaxDynamicSharedMemorySize, SMEM_TOTAL);
    dim3 grid(MTOK / BM, NOUT / BN);   // 8 x 16 = 128 CTAs
    SBNLinear_39754217292616_kernel<<<grid, THREADS, SMEM_TOTAL>>>(s, out);
}

// round 4
// speedup vs baseline: 1.1400x; 1.0711x over previous
#include <cuda_runtime.h>
#include <cuda_fp16.h>
#include <cstdint>

#define DINL __device__ __forceinline__

namespace {
constexpr int KDIM = 4096;   // in_features
constexpr int NOUT = 4096;   // out_features
constexpr int MTOK = 1024;   // tokens

constexpr int BM = 128;      // CTA tile M
constexpr int BN = 256;      // CTA tile N
constexpr int BK = 32;       // K per stage
constexpr int NUM_K = KDIM / BK;   // 128
constexpr int STAGES = 4;
constexpr int THREADS = 256;

constexpr int A_ROW_B = 80;                 // 32 halves (64B) + 16B pad -> conflict-free ldmatrix
constexpr int B_ROW_B = 80;
constexpr int A_BYTES = BM * A_ROW_B;       // 10240
constexpr int B_BYTES = BN * B_ROW_B;       // 20480
constexpr int STAGE_BYTES = A_BYTES + B_BYTES;   // 30720
constexpr int SMEM_TOTAL = STAGES * STAGE_BYTES; // 122880

constexpr int CONV_BLOCKS = (MTOK * KDIM / 4) / 256;            // 4096
constexpr int PACK_BLOCKS = (NOUT * (KDIM / 128) * 32) / 256;   // 16384
}  // namespace

// Scratch (static device globals: allowed; no runtime allocation).
__device__ __align__(16) __half   g_xh[(size_t)MTOK * KDIM];          // 8 MB fp16 x
__device__ __align__(16) unsigned g_wbits[(KDIM / 32) * NOUT];        // 2 MB packed binarized W, [kchunk][n]

DINL uint32_t smem_u32(const void* p) {
    uint32_t a;
    asm("{ .reg .u64 t; cvta.to.shared.u64 t, %1; cvt.u32.u64 %0, t; }" : "=r"(a) : "l"(p));
    return a;
}

// ---------------- fused prepass: x->fp16  +  binarize/bit-pack W ----------------
__global__ void __launch_bounds__(256) prepass_kernel(const float* __restrict__ x,
                                                      const float* __restrict__ w) {
    if (blockIdx.x < CONV_BLOCKS) {
        int i = blockIdx.x * blockDim.x + threadIdx.x;
        float4 v = __ldcs((const float4*)x + i);            // read-once: stream past L2
        __half2 h0 = __floats2half2_rn(v.x, v.y);
        __half2 h1 = __floats2half2_rn(v.z, v.w);
        uint2 u;
        u.x = *(const uint32_t*)&h0;
        u.y = *(const uint32_t*)&h1;
        *(uint2*)(&g_xh[(size_t)i * 4]) = u;                // re-read by GEMM: keep cacheable
    } else {
        // one warp packs 128 K-values (float4/lane) of one W row into 4 bit-words
        int pb = blockIdx.x - CONV_BLOCKS;
        int lane = threadIdx.x & 31;
        int wg = pb * 8 + (threadIdx.x >> 5);   // global warp id
        int n = wg & (NOUT - 1);
        int kb = wg >> 12;                      // 128-wide K block, 0..31
        const float4 v = __ldcs((const float4*)(w + (size_t)n * KDIM + kb * 128) + lane);
        unsigned nib = (v.x > 0.f ? 1u : 0u) | (v.y > 0.f ? 2u : 0u)
                     | (v.z > 0.f ? 4u : 0u) | (v.w > 0.f ? 8u : 0u);
        unsigned a = nib | (__shfl_down_sync(0xFFFFFFFFu, nib, 1) << 4);
        unsigned b = a   | (__shfl_down_sync(0xFFFFFFFFu, a, 2)   << 8);
        unsigned m = b   | (__shfl_down_sync(0xFFFFFFFFu, b, 4)   << 16);
        if ((lane & 7) == 0) {
            int c = kb * 4 + (lane >> 3);
            g_wbits[c * NOUT + n] = m;
        }
    }
}

// ---------------- main GEMM: out = (x_fp16 @ Wb^T) * round(max(s,1)) ----------------
// f16-accumulate HMMA (2x rate); fp32 promotion every 2 K-chunks done ON the tensor
// pipe via identity-B f32-accum HMMAs (f16 D-fragment reused as A-fragment).
__global__ void __launch_bounds__(THREADS, 1)
SBNLinear_39754217292616_kernel(const float* __restrict__ s, float* __restrict__ out) {
    extern __shared__ char smem[];
    const uint32_t sb = smem_u32(smem);
    const int tid = threadIdx.x;
    const int lane = tid & 31;
    const int wid = tid >> 5;
    const int m0 = blockIdx.x * BM;
    const int n0 = blockIdx.y * BN;
    const int m_off = (wid >> 2) * 64;     // 2 warps in M
    const int n_off = (wid & 3) * 64;      // 4 warps in N

    // identity B-fragment (fp16 I8), same register for both k-halves
    const int q = lane >> 2, p = lane & 3;
    const uint32_t idf = ((2 * p == q) ? 0x3C00u : 0u) | ((2 * p + 1 == q) ? 0x3C000000u : 0u);
    const uint32_t zf = 0u;

    float acc32[4][8][4];
    uint32_t acc16[4][8][2];
    #pragma unroll
    for (int mi = 0; mi < 4; ++mi)
        #pragma unroll
        for (int nj = 0; nj < 8; ++nj) {
            acc16[mi][nj][0] = 0u; acc16[mi][nj][1] = 0u;
            #pragma unroll
            for (int e = 0; e < 4; ++e) acc32[mi][nj][e] = 0.0f;
        }

    auto issueA = [&](int c, int buf) {
        #pragma unroll
        for (int i = 0; i < 2; ++i) {
            int qx = tid + i * THREADS;          // 0..511
            int row = qx >> 2;
            int ch = qx & 3;
            uint32_t dst = sb + buf * STAGE_BYTES + row * A_ROW_B + ch * 16;
            const __half* src = &g_xh[(size_t)(m0 + row) * KDIM + c * BK + ch * 8];
            asm volatile("cp.async.cg.shared.global [%0], [%1], 16;\n" :: "r"(dst), "l"(src) : "memory");
        }
    };
    auto stsB = [&](unsigned bits, int buf) {
        uint32_t dst = sb + buf * STAGE_BYTES + A_BYTES + tid * B_ROW_B;
        #pragma unroll
        for (int j = 0; j < 4; ++j) {
            uint32_t u0, u1, u2, u3;
            int pp = j * 8;
            u0 = ((bits >> (pp + 0)) & 1 ? 0x3C00u : 0u) | ((bits >> (pp + 1)) & 1 ? 0x3C000000u : 0u);
            u1 = ((bits >> (pp + 2)) & 1 ? 0x3C00u : 0u) | ((bits >> (pp + 3)) & 1 ? 0x3C000000u : 0u);
            u2 = ((bits >> (pp + 4)) & 1 ? 0x3C00u : 0u) | ((bits >> (pp + 5)) & 1 ? 0x3C000000u : 0u);
            u3 = ((bits >> (pp + 6)) & 1 ? 0x3C00u : 0u) | ((bits >> (pp + 7)) & 1 ? 0x3C000000u : 0u);
            asm volatile("st.shared.v4.b32 [%0], {%1,%2,%3,%4};\n"
                         :: "r"(dst + j * 16), "r"(u0), "r"(u1), "r"(u2), "r"(u3) : "memory");
        }
    };

    // prologue: stages 0..2
    #pragma unroll
    for (int c = 0; c < STAGES - 1; ++c) {
        issueA(c, c);
        asm volatile("cp.async.commit_group;\n" ::: "memory");
        unsigned bits = g_wbits[c * NOUT + n0 + tid];
        stsB(bits, c);
    }
    unsigned bits_next = g_wbits[3 * NOUT + n0 + tid];

    for (int c = 0; c < NUM_K; ++c) {
        const int buf = c & 3;
        if (c < NUM_K - 2)       asm volatile("cp.async.wait_group 2;\n" ::: "memory");
        else if (c == NUM_K - 2) asm volatile("cp.async.wait_group 1;\n" ::: "memory");
        else                     asm volatile("cp.async.wait_group 0;\n" ::: "memory");
        __syncthreads();

        const int cn = c + 3;
        if (cn < NUM_K) {
            const int nbuf = cn & 3;
            stsB(bits_next, nbuf);
            issueA(cn, nbuf);
            asm volatile("cp.async.commit_group;\n" ::: "memory");
            if (cn + 1 < NUM_K)
                bits_next = g_wbits[(cn + 1) * NOUT + n0 + tid];
        }

        const uint32_t ab = sb + buf * STAGE_BYTES;
        const uint32_t bb = ab + A_BYTES;
        #pragma unroll
        for (int h = 0; h < 2; ++h) {
            uint32_t a[4][4];
            #pragma unroll
            for (int mi = 0; mi < 4; ++mi) {
                uint32_t addr = ab + (uint32_t)(m_off + 16 * mi + (lane & 15)) * A_ROW_B
                                   + (uint32_t)(2 * h + (lane >> 4)) * 16;
                asm volatile("ldmatrix.sync.aligned.m8n8.x4.shared.b16 {%0,%1,%2,%3}, [%4];\n"
                             : "=r"(a[mi][0]), "=r"(a[mi][1]), "=r"(a[mi][2]), "=r"(a[mi][3])
                             : "r"(addr));
            }
            #pragma unroll
            for (int g = 0; g < 4; ++g) {
                int row = n_off + 16 * g + ((lane >> 4) << 3) + (lane & 7);
                uint32_t addr = bb + (uint32_t)row * B_ROW_B
                                   + (uint32_t)(2 * h + ((lane >> 3) & 1)) * 16;
                uint32_t r0, r1, r2, r3;
                asm volatile("ldmatrix.sync.aligned.m8n8.x4.shared.b16 {%0,%1,%2,%3}, [%4];\n"
                             : "=r"(r0), "=r"(r1), "=r"(r2), "=r"(r3) : "r"(addr));
                #pragma unroll
                for (int mi = 0; mi < 4; ++mi) {
                    asm volatile(
                        "mma.sync.aligned.m16n8k16.row.col.f16.f16.f16.f16 "
                        "{%0,%1}, {%2,%3,%4,%5}, {%6,%7}, {%0,%1};\n"
                        : "+r"(acc16[mi][2 * g][0]), "+r"(acc16[mi][2 * g][1])
                        : "r"(a[mi][0]), "r"(a[mi][1]), "r"(a[mi][2]), "r"(a[mi][3]),
                          "r"(r0), "r"(r1));
                    asm volatile(
                        "mma.sync.aligned.m16n8k16.row.col.f16.f16.f16.f16 "
                        "{%0,%1}, {%2,%3,%4,%5}, {%6,%7}, {%0,%1};\n"
                        : "+r"(acc16[mi][2 * g + 1][0]), "+r"(acc16[mi][2 * g + 1][1])
                        : "r"(a[mi][0]), "r"(a[mi][1]), "r"(a[mi][2]), "r"(a[mi][3]),
                          "r"(r2), "r"(r3));
                }
            }
        }

        // promote f16 segment accumulators into fp32 every 2 chunks, on the TENSOR pipe:
        // acc32[2g]   += [acc16[2g] | acc16[2g+1]] x [I8; 0]
        // acc32[2g+1] += [acc16[2g] | acc16[2g+1]] x [0; I8]
        if (c & 1) {
            #pragma unroll
            for (int mi = 0; mi < 4; ++mi)
                #pragma unroll
                for (int g = 0; g < 4; ++g) {
                    asm volatile(
                        "mma.sync.aligned.m16n8k16.row.col.f32.f16.f16.f32 "
                        "{%0,%1,%2,%3}, {%4,%5,%6,%7}, {%8,%9}, {%0,%1,%2,%3};\n"
                        : "+f"(acc32[mi][2 * g][0]), "+f"(acc32[mi][2 * g][1]),
                          "+f"(acc32[mi][2 * g][2]), "+f"(acc32[mi][2 * g][3])
                        : "r"(acc16[mi][2 * g][0]), "r"(acc16[mi][2 * g][1]),
                          "r"(acc16[mi][2 * g + 1][0]), "r"(acc16[mi][2 * g + 1][1]),
                          "r"(idf), "r"(zf));
                    asm volatile(
                        "mma.sync.aligned.m16n8k16.row.col.f32.f16.f16.f32 "
                        "{%0,%1,%2,%3}, {%4,%5,%6,%7}, {%8,%9}, {%0,%1,%2,%3};\n"
                        : "+f"(acc32[mi][2 * g + 1][0]), "+f"(acc32[mi][2 * g + 1][1]),
                          "+f"(acc32[mi][2 * g + 1][2]), "+f"(acc32[mi][2 * g + 1][3])
                        : "r"(acc16[mi][2 * g][0]), "r"(acc16[mi][2 * g][1]),
                          "r"(acc16[mi][2 * g + 1][0]), "r"(acc16[mi][2 * g + 1][1]),
                          "r"(zf), "r"(idf));
                    acc16[mi][2 * g][0] = 0u;     acc16[mi][2 * g][1] = 0u;
                    acc16[mi][2 * g + 1][0] = 0u; acc16[mi][2 * g + 1][1] = 0u;
                }
        }
    }

    // epilogue: fuse s_eff = rint(max(s,1)) and store
    float sc[8][2];
    #pragma unroll
    for (int nj = 0; nj < 8; ++nj) {
        int col = n0 + n_off + 8 * nj + 2 * (lane & 3);
        sc[nj][0] = rintf(fmaxf(s[col], 1.0f));
        sc[nj][1] = rintf(fmaxf(s[col + 1], 1.0f));
    }
    #pragma unroll
    for (int mi = 0; mi < 4; ++mi) {
        int r0 = m0 + m_off + 16 * mi + (lane >> 2);
        #pragma unroll
        for (int nj = 0; nj < 8; ++nj) {
            int col = n0 + n_off + 8 * nj + 2 * (lane & 3);
            float2 v0 = make_float2(acc32[mi][nj][0] * sc[nj][0], acc32[mi][nj][1] * sc[nj][1]);
            float2 v1 = make_float2(acc32[mi][nj][2] * sc[nj][0], acc32[mi][nj][3] * sc[nj][1]);
            *(float2*)(out + (size_t)r0 * NOUT + col) = v0;
            *(float2*)(out + (size_t)(r0 + 8) * NOUT + col) = v1;
        }
    }
}

extern "C" void kernel_launch(void* const* d_in, const int* in_sizes, int n_in,
                              void* d_out, int out_size) {
    (void)in_sizes; (void)n_in; (void)out_size;
    const float* x = (const float*)d_in[0];
    const float* w = (const float*)d_in[1];
    const float* s = (const float*)d_in[2];
    float* out = (float*)d_out;

    prepass_kernel<<<CONV_BLOCKS + PACK_BLOCKS, 256>>>(x, w);

    cudaFuncSetAttribute(SBNLinear_39754217292616_kernel,
                         cudaFuncAttributeMaxDynamicSharedMemorySize, SMEM_TOTAL);
    dim3 grid(MTOK / BM, NOUT / BN);   // 8 x 16 = 128 CTAs
    SBNLinear_39754217292616_kernel<<<grid, THREADS, SMEM_TOTAL>>>(s, out);
}